// round 6
// baseline (speedup 1.0000x reference)
#include <cuda_runtime.h>
#include <cuda_bf16.h>
#include <math.h>

// 3-layer GCN, N=50000, E=800000, dims 128->64->64->32.
// hs = (h@W)*dis ; out[d] = dis[d]*(hs[d] + sum_{src->d} hs[src]) + b
// CSR-by-dst gather, no atomics in the hot path, packed f32x2 GEMMs.

#define NMAX 50000
#define EMAX 800000

__device__ float g_hs [NMAX * 64];
__device__ float g_hA [NMAX * 64];
__device__ float g_hB [NMAX * 64];
__device__ float g_dis[NMAX];
__device__ int   g_deg[NMAX];
__device__ int   g_rowptr[NMAX + 1];
__device__ int   g_cursor[NMAX];
__device__ int   g_col[EMAX];

// ---------------------------------------------------------------------------
// packed f32x2 helpers (sm_103a)
// ---------------------------------------------------------------------------
__device__ __forceinline__ unsigned long long pack2(float a, float b) {
    unsigned long long r;
    asm("mov.b64 %0, {%1, %2};" : "=l"(r) : "f"(a), "f"(b));
    return r;
}
__device__ __forceinline__ unsigned long long ffma2(unsigned long long a,
                                                    unsigned long long b,
                                                    unsigned long long c) {
    unsigned long long d;
    asm("fma.rn.f32x2 %0, %1, %2, %3;" : "=l"(d) : "l"(a), "l"(b), "l"(c));
    return d;
}
__device__ __forceinline__ unsigned long long fmul2(unsigned long long a,
                                                    unsigned long long b) {
    unsigned long long d;
    asm("mul.rn.f32x2 %0, %1, %2;" : "=l"(d) : "l"(a), "l"(b));
    return d;
}

// ---------------------------------------------------------------------------
// CSR build
// ---------------------------------------------------------------------------
__global__ void deg_zero_kernel(int* deg, int n) {
    int i = blockIdx.x * blockDim.x + threadIdx.x;
    if (i < n) deg[i] = 0;
}

__global__ void deg_count_kernel(const int* __restrict__ dst, int* deg, int e) {
    int i = blockIdx.x * blockDim.x + threadIdx.x;
    if (i < e) atomicAdd(&deg[dst[i]], 1);
}

// Single-block fused scan: exclusive prefix of deg -> rowptr/cursor, plus dis.
// Tile-wise (1024/tile) warp-shuffle scan, coalesced loads.
__global__ void scan_fixup_kernel(const int* __restrict__ deg,
                                  int* rowptr, int* cursor, float* dis,
                                  int n, int e) {
    __shared__ int warpsum[32];
    __shared__ int carry;
    const int tid = threadIdx.x;
    const int lane = tid & 31;
    const int wid = tid >> 5;
    if (tid == 0) carry = 0;
    __syncthreads();

    for (int base = 0; base < n; base += 1024) {
        int i = base + tid;
        int d = (i < n) ? deg[i] : 0;
        // inclusive warp scan of d
        int v = d;
#pragma unroll
        for (int off = 1; off < 32; off <<= 1) {
            int u = __shfl_up_sync(0xFFFFFFFFu, v, off);
            if (lane >= off) v += u;
        }
        if (lane == 31) warpsum[wid] = v;
        __syncthreads();
        if (wid == 0) {
            int w = warpsum[lane];
#pragma unroll
            for (int off = 1; off < 32; off <<= 1) {
                int u = __shfl_up_sync(0xFFFFFFFFu, w, off);
                if (lane >= off) w += u;
            }
            warpsum[lane] = w;  // inclusive scan of warp totals
        }
        __syncthreads();
        int blockpref = (wid > 0) ? warpsum[wid - 1] : 0;
        int excl = carry + blockpref + (v - d);
        if (i < n) {
            rowptr[i] = excl;
            cursor[i] = excl;
            dis[i] = rsqrtf((float)(d + 1));  // +1 self loop
        }
        __syncthreads();
        if (tid == 0) carry += warpsum[31];
        __syncthreads();
    }
    if (tid == 0) rowptr[n] = e;
}

__global__ void fill_kernel(const int* __restrict__ src,
                            const int* __restrict__ dst,
                            int* cursor, int* col, int e) {
    int i = blockIdx.x * blockDim.x + threadIdx.x;
    if (i < e) {
        int p = atomicAdd(&cursor[dst[i]], 1);
        col[p] = src[i];
    }
}

// ---------------------------------------------------------------------------
// GEMM + pre-scale: hs[row,:] = (in[row,:] @ W) * dis[row]
// Thread-per-row, W broadcast from shared, packed f32x2 FMAs.
// ---------------------------------------------------------------------------
template <int IN, int OUT>
__global__ void gemm_kernel(const float* __restrict__ in,
                            const float* __restrict__ W,
                            const float* __restrict__ dis,
                            float* __restrict__ hs, int n) {
    __shared__ __align__(16) float sW[IN * OUT];
    for (int i = threadIdx.x; i < IN * OUT / 4; i += blockDim.x)
        reinterpret_cast<float4*>(sW)[i] = reinterpret_cast<const float4*>(W)[i];
    __syncthreads();

    int row = blockIdx.x * blockDim.x + threadIdx.x;
    if (row >= n) return;

    unsigned long long acc[OUT / 2];
#pragma unroll
    for (int c = 0; c < OUT / 2; c++) acc[c] = 0ULL;

    const float* xr = in + (size_t)row * IN;
    for (int k0 = 0; k0 < IN; k0 += 4) {
        float4 xv = *reinterpret_cast<const float4*>(xr + k0);
        float xs[4] = {xv.x, xv.y, xv.z, xv.w};
#pragma unroll
        for (int kk = 0; kk < 4; kk++) {
            unsigned long long xx = pack2(xs[kk], xs[kk]);
            const ulonglong2* wr =
                reinterpret_cast<const ulonglong2*>(sW + (k0 + kk) * OUT);
#pragma unroll
            for (int c4 = 0; c4 < OUT / 4; c4++) {
                ulonglong2 w = wr[c4];
                acc[c4 * 2 + 0] = ffma2(xx, w.x, acc[c4 * 2 + 0]);
                acc[c4 * 2 + 1] = ffma2(xx, w.y, acc[c4 * 2 + 1]);
            }
        }
    }

    float d = dis[row];
    unsigned long long dd = pack2(d, d);
    ulonglong2* hp = reinterpret_cast<ulonglong2*>(hs + (size_t)row * OUT);
#pragma unroll
    for (int c4 = 0; c4 < OUT / 4; c4++) {
        ulonglong2 r;
        r.x = fmul2(acc[c4 * 2 + 0], dd);
        r.y = fmul2(acc[c4 * 2 + 1], dd);
        hp[c4] = r;
    }
}

// ---------------------------------------------------------------------------
// Gather + finalize: out[d,:] = [relu]( dis[d]*(hs[d,:] + sum_in hs[src,:]) + b )
// OUT/4 lanes per node. Software-pipelined: batch 8 indices, then 8
// independent float4 loads -> MLP ~8, breaking the col->hs dependent chain.
// ---------------------------------------------------------------------------
template <int OUT, bool RELU>
__global__ void gather_kernel(const int* __restrict__ rowptr,
                              const int* __restrict__ col,
                              const float* __restrict__ hs,
                              const float* __restrict__ dis,
                              const float* __restrict__ bias,
                              float* __restrict__ out, int n) {
    const int G = OUT / 4;
    int t = blockIdx.x * blockDim.x + threadIdx.x;
    int gid = t / G;
    int lane = t % G;
    if (gid >= n) return;

    const float4* hs4 = reinterpret_cast<const float4*>(hs);
    int beg = rowptr[gid];
    int end = rowptr[gid + 1];

    float4 a0 = hs4[(size_t)gid * G + lane];  // self term
    float4 a1 = make_float4(0.f, 0.f, 0.f, 0.f);

    int e = beg;
    for (; e + 8 <= end; e += 8) {
        int s[8];
#pragma unroll
        for (int j = 0; j < 8; j++) s[j] = __ldg(&col[e + j]);
        float4 v[8];
#pragma unroll
        for (int j = 0; j < 8; j++) v[j] = hs4[(size_t)s[j] * G + lane];
#pragma unroll
        for (int j = 0; j < 8; j += 2) {
            a0.x += v[j].x;     a0.y += v[j].y;
            a0.z += v[j].z;     a0.w += v[j].w;
            a1.x += v[j + 1].x; a1.y += v[j + 1].y;
            a1.z += v[j + 1].z; a1.w += v[j + 1].w;
        }
    }
    for (; e < end; e++) {
        int s = __ldg(&col[e]);
        float4 v = hs4[(size_t)s * G + lane];
        a0.x += v.x; a0.y += v.y; a0.z += v.z; a0.w += v.w;
    }
    a0.x += a1.x; a0.y += a1.y; a0.z += a1.z; a0.w += a1.w;

    float d = dis[gid];
    float4 b4 = reinterpret_cast<const float4*>(bias)[lane];
    float4 r;
    r.x = a0.x * d + b4.x;
    r.y = a0.y * d + b4.y;
    r.z = a0.z * d + b4.z;
    r.w = a0.w * d + b4.w;
    if (RELU) {
        r.x = fmaxf(r.x, 0.0f);
        r.y = fmaxf(r.y, 0.0f);
        r.z = fmaxf(r.z, 0.0f);
        r.w = fmaxf(r.w, 0.0f);
    }
    reinterpret_cast<float4*>(out)[(size_t)gid * G + lane] = r;
}

// ---------------------------------------------------------------------------
// launch
// ---------------------------------------------------------------------------
extern "C" void kernel_launch(void* const* d_in, const int* in_sizes, int n_in,
                              void* d_out, int out_size) {
    const float* x    = (const float*)d_in[0];
    const int*   eidx = (const int*)  d_in[1];
    const float* W1   = (const float*)d_in[2];
    const float* b1   = (const float*)d_in[3];
    const float* W2   = (const float*)d_in[4];
    const float* b2   = (const float*)d_in[5];
    const float* W3   = (const float*)d_in[6];
    const float* b3   = (const float*)d_in[7];

    const int N = in_sizes[0] / 128;
    const int E = in_sizes[1] / 2;
    const int* esrc = eidx;
    const int* edst = eidx + E;

    float *hs, *hA, *hB, *dis;
    int *deg, *rowptr, *cursor, *col;
    cudaGetSymbolAddress((void**)&hs,     g_hs);
    cudaGetSymbolAddress((void**)&hA,     g_hA);
    cudaGetSymbolAddress((void**)&hB,     g_hB);
    cudaGetSymbolAddress((void**)&dis,    g_dis);
    cudaGetSymbolAddress((void**)&deg,    g_deg);
    cudaGetSymbolAddress((void**)&rowptr, g_rowptr);
    cudaGetSymbolAddress((void**)&cursor, g_cursor);
    cudaGetSymbolAddress((void**)&col,    g_col);

    float* out = (float*)d_out;
    const int T = 256;

    // --- CSR build + normalization (4 launches) ---
    deg_zero_kernel  <<<(N + T - 1) / T, T>>>(deg, N);
    deg_count_kernel <<<(E + T - 1) / T, T>>>(edst, deg, E);
    scan_fixup_kernel<<<1, 1024>>>(deg, rowptr, cursor, dis, N, E);
    fill_kernel      <<<(E + T - 1) / T, T>>>(esrc, edst, cursor, col, E);

    // --- layer 1: 128 -> 64, relu ---
    gemm_kernel<128, 64><<<(N + 127) / 128, 128>>>(x, W1, dis, hs, N);
    gather_kernel<64, true><<<(N * 16 + T - 1) / T, T>>>(rowptr, col, hs, dis, b1, hA, N);

    // --- layer 2: 64 -> 64, relu ---
    gemm_kernel<64, 64><<<(N + 127) / 128, 128>>>(hA, W2, dis, hs, N);
    gather_kernel<64, true><<<(N * 16 + T - 1) / T, T>>>(rowptr, col, hs, dis, b2, hB, N);

    // --- layer 3: 64 -> 32, no relu ---
    gemm_kernel<64, 32><<<(N + 127) / 128, 128>>>(hB, W3, dis, hs, N);
    gather_kernel<32, false><<<(N * 8 + T - 1) / T, T>>>(rowptr, col, hs, dis, b3, out, N);
}

// round 7
// speedup vs baseline: 1.2312x; 1.2312x over previous
#include <cuda_runtime.h>
#include <cuda_bf16.h>
#include <math.h>

// 3-layer GCN, N=50000, E=800000, dims 128->64->64->32.
// hs = (h@W)*dis ; out[d] = dis[d]*(hs[d] + sum_{src->d} hs[src]) + b
// CSR-by-dst gather, packed f32x2 GEMMs.

#define NMAX 50000
#define EMAX 800000

__device__ float g_hs [NMAX * 64];
__device__ float g_hA [NMAX * 64];
__device__ float g_hB [NMAX * 64];
__device__ float g_dis[NMAX];
__device__ int   g_deg[NMAX];
__device__ int   g_scan[NMAX];
__device__ int   g_bsum[64];
__device__ int   g_rowptr[NMAX + 1];
__device__ int   g_cursor[NMAX];
__device__ int   g_col[EMAX];

// ---------------------------------------------------------------------------
// packed f32x2 helpers (sm_103a)
// ---------------------------------------------------------------------------
__device__ __forceinline__ unsigned long long pack2(float a, float b) {
    unsigned long long r;
    asm("mov.b64 %0, {%1, %2};" : "=l"(r) : "f"(a), "f"(b));
    return r;
}
__device__ __forceinline__ unsigned long long ffma2(unsigned long long a,
                                                    unsigned long long b,
                                                    unsigned long long c) {
    unsigned long long d;
    asm("fma.rn.f32x2 %0, %1, %2, %3;" : "=l"(d) : "l"(a), "l"(b), "l"(c));
    return d;
}
__device__ __forceinline__ unsigned long long fmul2(unsigned long long a,
                                                    unsigned long long b) {
    unsigned long long d;
    asm("mul.rn.f32x2 %0, %1, %2;" : "=l"(d) : "l"(a), "l"(b));
    return d;
}

// ---------------------------------------------------------------------------
// CSR build
// ---------------------------------------------------------------------------
__global__ void deg_count_kernel(const int* __restrict__ dst, int* deg, int e) {
    int q = blockIdx.x * blockDim.x + threadIdx.x;
    int base = q * 4;
    if (base + 4 <= e) {
        int4 d4 = *reinterpret_cast<const int4*>(dst + base);
        atomicAdd(&deg[d4.x], 1);
        atomicAdd(&deg[d4.y], 1);
        atomicAdd(&deg[d4.z], 1);
        atomicAdd(&deg[d4.w], 1);
    } else {
        for (int i = base; i < e; i++) atomicAdd(&deg[dst[i]], 1);
    }
}

__global__ void scan1_kernel(const int* __restrict__ deg, int* scanout,
                             int* bsum, int n) {
    __shared__ int s[1024];
    int i = blockIdx.x * 1024 + threadIdx.x;
    int v = (i < n) ? deg[i] : 0;
    s[threadIdx.x] = v;
    __syncthreads();
#pragma unroll
    for (int off = 1; off < 1024; off <<= 1) {
        int add = (threadIdx.x >= off) ? s[threadIdx.x - off] : 0;
        __syncthreads();
        s[threadIdx.x] += add;
        __syncthreads();
    }
    if (i < n) scanout[i] = s[threadIdx.x];
    if (threadIdx.x == 1023) bsum[blockIdx.x] = s[1023];
}

__global__ void scan2_kernel(int* bsum, int nb) {
    __shared__ int s[64];
    if (threadIdx.x < nb) s[threadIdx.x] = bsum[threadIdx.x];
    __syncthreads();
    if (threadIdx.x == 0) {
        int run = 0;
        for (int j = 0; j < nb; j++) { int t = s[j]; s[j] = run; run += t; }
    }
    __syncthreads();
    if (threadIdx.x < nb) bsum[threadIdx.x] = s[threadIdx.x];
}

__global__ void fixup_kernel(const int* __restrict__ scanin,
                             const int* __restrict__ deg,
                             const int* __restrict__ bsum,
                             int* rowptr, int* cursor, float* dis,
                             int n, int e) {
    int i = blockIdx.x * blockDim.x + threadIdx.x;
    if (i < n) {
        int rp = scanin[i] - deg[i] + bsum[i >> 10];  // exclusive prefix
        rowptr[i] = rp;
        cursor[i] = rp;
        dis[i] = rsqrtf((float)(deg[i] + 1));         // +1 self loop
    }
    if (i == 0) rowptr[n] = e;
}

__global__ void fill_kernel(const int* __restrict__ src,
                            const int* __restrict__ dst,
                            int* cursor, int* col, int e) {
    int q = blockIdx.x * blockDim.x + threadIdx.x;
    int base = q * 4;
    if (base + 4 <= e) {
        int4 s4 = *reinterpret_cast<const int4*>(src + base);
        int4 d4 = *reinterpret_cast<const int4*>(dst + base);
        // 4 independent atomic->store chains: 4x the MLP of scalar version
        int p0 = atomicAdd(&cursor[d4.x], 1);
        int p1 = atomicAdd(&cursor[d4.y], 1);
        int p2 = atomicAdd(&cursor[d4.z], 1);
        int p3 = atomicAdd(&cursor[d4.w], 1);
        col[p0] = s4.x;
        col[p1] = s4.y;
        col[p2] = s4.z;
        col[p3] = s4.w;
    } else {
        for (int i = base; i < e; i++) {
            int p = atomicAdd(&cursor[dst[i]], 1);
            col[p] = src[i];
        }
    }
}

// ---------------------------------------------------------------------------
// GEMM + pre-scale: hs[row,:] = (in[row,:] @ W) * dis[row]
// Thread-per-row, W broadcast from shared, packed f32x2 FMAs.
// ---------------------------------------------------------------------------
template <int IN, int OUT>
__global__ void gemm_kernel(const float* __restrict__ in,
                            const float* __restrict__ W,
                            const float* __restrict__ dis,
                            float* __restrict__ hs, int n) {
    __shared__ __align__(16) float sW[IN * OUT];
    for (int i = threadIdx.x; i < IN * OUT / 4; i += blockDim.x)
        reinterpret_cast<float4*>(sW)[i] = reinterpret_cast<const float4*>(W)[i];
    __syncthreads();

    int row = blockIdx.x * blockDim.x + threadIdx.x;
    if (row >= n) return;

    unsigned long long acc[OUT / 2];
#pragma unroll
    for (int c = 0; c < OUT / 2; c++) acc[c] = 0ULL;

    const float* xr = in + (size_t)row * IN;
    for (int k0 = 0; k0 < IN; k0 += 4) {
        float4 xv = *reinterpret_cast<const float4*>(xr + k0);
        float xs[4] = {xv.x, xv.y, xv.z, xv.w};
#pragma unroll
        for (int kk = 0; kk < 4; kk++) {
            unsigned long long xx = pack2(xs[kk], xs[kk]);
            const ulonglong2* wr =
                reinterpret_cast<const ulonglong2*>(sW + (k0 + kk) * OUT);
#pragma unroll
            for (int c4 = 0; c4 < OUT / 4; c4++) {
                ulonglong2 w = wr[c4];
                acc[c4 * 2 + 0] = ffma2(xx, w.x, acc[c4 * 2 + 0]);
                acc[c4 * 2 + 1] = ffma2(xx, w.y, acc[c4 * 2 + 1]);
            }
        }
    }

    float d = dis[row];
    unsigned long long dd = pack2(d, d);
    ulonglong2* hp = reinterpret_cast<ulonglong2*>(hs + (size_t)row * OUT);
#pragma unroll
    for (int c4 = 0; c4 < OUT / 4; c4++) {
        ulonglong2 r;
        r.x = fmul2(acc[c4 * 2 + 0], dd);
        r.y = fmul2(acc[c4 * 2 + 1], dd);
        hp[c4] = r;
    }
}

// ---------------------------------------------------------------------------
// Gather + finalize: out[d,:] = [relu]( dis[d]*(hs[d,:] + sum_in hs[src,:]) + b )
// OUT/4 lanes per node; each lane owns one float4 chunk. Explicit 4-deep
// index/value batch: MLP ~4 without the register-pressure cliff of 8.
// ---------------------------------------------------------------------------
template <int OUT, bool RELU>
__global__ void gather_kernel(const int* __restrict__ rowptr,
                              const int* __restrict__ col,
                              const float* __restrict__ hs,
                              const float* __restrict__ dis,
                              const float* __restrict__ bias,
                              float* __restrict__ out, int n) {
    const int G = OUT / 4;
    int t = blockIdx.x * blockDim.x + threadIdx.x;
    int gid = t / G;
    int lane = t % G;
    if (gid >= n) return;

    const float4* hs4 = reinterpret_cast<const float4*>(hs);
    int beg = rowptr[gid];
    int end = rowptr[gid + 1];

    float4 a0 = hs4[(size_t)gid * G + lane];  // self term
    float4 a1 = make_float4(0.f, 0.f, 0.f, 0.f);

    int e = beg;
    for (; e + 4 <= end; e += 4) {
        int s0 = __ldg(&col[e + 0]);
        int s1 = __ldg(&col[e + 1]);
        int s2 = __ldg(&col[e + 2]);
        int s3 = __ldg(&col[e + 3]);
        float4 v0 = hs4[(size_t)s0 * G + lane];
        float4 v1 = hs4[(size_t)s1 * G + lane];
        float4 v2 = hs4[(size_t)s2 * G + lane];
        float4 v3 = hs4[(size_t)s3 * G + lane];
        a0.x += v0.x; a0.y += v0.y; a0.z += v0.z; a0.w += v0.w;
        a1.x += v1.x; a1.y += v1.y; a1.z += v1.z; a1.w += v1.w;
        a0.x += v2.x; a0.y += v2.y; a0.z += v2.z; a0.w += v2.w;
        a1.x += v3.x; a1.y += v3.y; a1.z += v3.z; a1.w += v3.w;
    }
    for (; e < end; e++) {
        int s = __ldg(&col[e]);
        float4 v = hs4[(size_t)s * G + lane];
        a0.x += v.x; a0.y += v.y; a0.z += v.z; a0.w += v.w;
    }
    a0.x += a1.x; a0.y += a1.y; a0.z += a1.z; a0.w += a1.w;

    float d = dis[gid];
    float4 b4 = reinterpret_cast<const float4*>(bias)[lane];
    float4 r;
    r.x = a0.x * d + b4.x;
    r.y = a0.y * d + b4.y;
    r.z = a0.z * d + b4.z;
    r.w = a0.w * d + b4.w;
    if (RELU) {
        r.x = fmaxf(r.x, 0.0f);
        r.y = fmaxf(r.y, 0.0f);
        r.z = fmaxf(r.z, 0.0f);
        r.w = fmaxf(r.w, 0.0f);
    }
    reinterpret_cast<float4*>(out)[(size_t)gid * G + lane] = r;
}

// ---------------------------------------------------------------------------
// launch
// ---------------------------------------------------------------------------
extern "C" void kernel_launch(void* const* d_in, const int* in_sizes, int n_in,
                              void* d_out, int out_size) {
    const float* x    = (const float*)d_in[0];
    const int*   eidx = (const int*)  d_in[1];
    const float* W1   = (const float*)d_in[2];
    const float* b1   = (const float*)d_in[3];
    const float* W2   = (const float*)d_in[4];
    const float* b2   = (const float*)d_in[5];
    const float* W3   = (const float*)d_in[6];
    const float* b3   = (const float*)d_in[7];

    const int N = in_sizes[0] / 128;
    const int E = in_sizes[1] / 2;
    const int* esrc = eidx;
    const int* edst = eidx + E;

    float *hs, *hA, *hB, *dis;
    int *deg, *scn, *bsum, *rowptr, *cursor, *col;
    cudaGetSymbolAddress((void**)&hs,     g_hs);
    cudaGetSymbolAddress((void**)&hA,     g_hA);
    cudaGetSymbolAddress((void**)&hB,     g_hB);
    cudaGetSymbolAddress((void**)&dis,    g_dis);
    cudaGetSymbolAddress((void**)&deg,    g_deg);
    cudaGetSymbolAddress((void**)&scn,    g_scan);
    cudaGetSymbolAddress((void**)&bsum,   g_bsum);
    cudaGetSymbolAddress((void**)&rowptr, g_rowptr);
    cudaGetSymbolAddress((void**)&cursor, g_cursor);
    cudaGetSymbolAddress((void**)&col,    g_col);

    float* out = (float*)d_out;
    const int T = 256;
    const int NB = (N + 1023) / 1024;
    const int EQ = (E + 3) / 4;  // quads for vectorized edge kernels

    // --- CSR build + normalization ---
    cudaMemsetAsync(deg, 0, (size_t)N * sizeof(int));
    deg_count_kernel<<<(EQ + T - 1) / T, T>>>(edst, deg, E);
    scan1_kernel    <<<NB, 1024>>>(deg, scn, bsum, N);
    scan2_kernel    <<<1, 64>>>(bsum, NB);
    fixup_kernel    <<<(N + T - 1) / T, T>>>(scn, deg, bsum, rowptr, cursor, dis, N, E);
    fill_kernel     <<<(EQ + T - 1) / T, T>>>(esrc, edst, cursor, col, E);

    // --- layer 1: 128 -> 64, relu ---
    gemm_kernel<128, 64><<<(N + 127) / 128, 128>>>(x, W1, dis, hs, N);
    gather_kernel<64, true><<<(N * 16 + T - 1) / T, T>>>(rowptr, col, hs, dis, b1, hA, N);

    // --- layer 2: 64 -> 64, relu ---
    gemm_kernel<64, 64><<<(N + 127) / 128, 128>>>(hA, W2, dis, hs, N);
    gather_kernel<64, true><<<(N * 16 + T - 1) / T, T>>>(rowptr, col, hs, dis, b2, hB, N);

    // --- layer 3: 64 -> 32, no relu ---
    gemm_kernel<64, 32><<<(N + 127) / 128, 128>>>(hB, W3, dis, hs, N);
    gather_kernel<32, false><<<(N * 8 + T - 1) / T, T>>>(rowptr, col, hs, dis, b3, out, N);
}

// round 9
// speedup vs baseline: 1.3200x; 1.0721x over previous
#include <cuda_runtime.h>
#include <cuda_bf16.h>
#include <math.h>

// 3-layer GCN, N=50000, E=800000, dims 128->64->64->32.
// Layer: out[d] = dis[d]*( sum_{s->d} dis[s]*h[s] + dis[d]*h[d] ) + b, h = in@W
// CSR-by-dst gather. CSR build runs on a forked stream concurrently with gemm1
// (gemm1 is dis-free; src normalization folded into gather1).

#define NMAX 50000
#define EMAX 800000

__device__ float g_hs [NMAX * 64];
__device__ float g_hA [NMAX * 64];
__device__ float g_hB [NMAX * 64];
__device__ float g_dis[NMAX];
__device__ int   g_deg[NMAX];
__device__ int   g_scan[NMAX];
__device__ int   g_bsum[64];
__device__ int   g_rowptr[NMAX + 1];
__device__ int   g_cursor[NMAX];
__device__ int   g_col[EMAX];

// ---------------------------------------------------------------------------
// packed f32x2 helpers (sm_103a)
// ---------------------------------------------------------------------------
__device__ __forceinline__ unsigned long long pack2(float a, float b) {
    unsigned long long r;
    asm("mov.b64 %0, {%1, %2};" : "=l"(r) : "f"(a), "f"(b));
    return r;
}
__device__ __forceinline__ unsigned long long ffma2(unsigned long long a,
                                                    unsigned long long b,
                                                    unsigned long long c) {
    unsigned long long d;
    asm("fma.rn.f32x2 %0, %1, %2, %3;" : "=l"(d) : "l"(a), "l"(b), "l"(c));
    return d;
}
__device__ __forceinline__ unsigned long long fmul2(unsigned long long a,
                                                    unsigned long long b) {
    unsigned long long d;
    asm("mul.rn.f32x2 %0, %1, %2;" : "=l"(d) : "l"(a), "l"(b));
    return d;
}

// ---------------------------------------------------------------------------
// CSR build
// ---------------------------------------------------------------------------
__global__ void deg_count_kernel(const int* __restrict__ dst, int* deg, int e) {
    int q = blockIdx.x * blockDim.x + threadIdx.x;
    int base = q * 4;
    if (base + 4 <= e) {
        int4 d4 = *reinterpret_cast<const int4*>(dst + base);
        atomicAdd(&deg[d4.x], 1);
        atomicAdd(&deg[d4.y], 1);
        atomicAdd(&deg[d4.z], 1);
        atomicAdd(&deg[d4.w], 1);
    } else {
        for (int i = base; i < e; i++) atomicAdd(&deg[dst[i]], 1);
    }
}

// Per-1024-tile inclusive scan of deg; tile totals to bsum.
__global__ void scan1_kernel(const int* __restrict__ deg, int* scanout,
                             int* bsum, int n) {
    __shared__ int s[1024];
    int i = blockIdx.x * 1024 + threadIdx.x;
    int v = (i < n) ? deg[i] : 0;
    s[threadIdx.x] = v;
    __syncthreads();
#pragma unroll
    for (int off = 1; off < 1024; off <<= 1) {
        int add = (threadIdx.x >= off) ? s[threadIdx.x - off] : 0;
        __syncthreads();
        s[threadIdx.x] += add;
        __syncthreads();
    }
    if (i < n) scanout[i] = s[threadIdx.x];
    if (threadIdx.x == 1023) bsum[blockIdx.x] = s[1023];
}

// Fixup with inlined bsum-prefix: each 256-thread block lies in one 1024-tile
// (tile = blockIdx.x>>2), so compute base = sum(bsum[0..tile)) via block reduce.
__global__ void fixup_kernel(const int* __restrict__ scanin,
                             const int* __restrict__ deg,
                             const int* __restrict__ bsum,
                             int* rowptr, int* cursor, float* dis,
                             int n, int e) {
    __shared__ int wsum[8];
    int tile = blockIdx.x >> 2;  // 256 threads/block, 1024 nodes/tile
    int part = 0;
    for (int j = threadIdx.x; j < tile; j += blockDim.x) part += bsum[j];
#pragma unroll
    for (int off = 16; off > 0; off >>= 1)
        part += __shfl_down_sync(0xFFFFFFFFu, part, off);
    if ((threadIdx.x & 31) == 0) wsum[threadIdx.x >> 5] = part;
    __syncthreads();
    if (threadIdx.x == 0) {
        int b = 0;
#pragma unroll
        for (int w = 0; w < 8; w++) b += wsum[w];
        wsum[0] = b;
    }
    __syncthreads();
    int base = wsum[0];

    int i = blockIdx.x * blockDim.x + threadIdx.x;
    if (i < n) {
        int d = deg[i];
        int rp = scanin[i] - d + base;  // exclusive prefix
        rowptr[i] = rp;
        cursor[i] = rp;
        dis[i] = rsqrtf((float)(d + 1));  // +1 self loop
    }
    if (i == 0) rowptr[n] = e;
}

__global__ void fill_kernel(const int* __restrict__ src,
                            const int* __restrict__ dst,
                            int* cursor, int* col, int e) {
    int q = blockIdx.x * blockDim.x + threadIdx.x;
    int base = q * 4;
    if (base + 4 <= e) {
        int4 s4 = *reinterpret_cast<const int4*>(src + base);
        int4 d4 = *reinterpret_cast<const int4*>(dst + base);
        int p0 = atomicAdd(&cursor[d4.x], 1);
        int p1 = atomicAdd(&cursor[d4.y], 1);
        int p2 = atomicAdd(&cursor[d4.z], 1);
        int p3 = atomicAdd(&cursor[d4.w], 1);
        col[p0] = s4.x;
        col[p1] = s4.y;
        col[p2] = s4.z;
        col[p3] = s4.w;
    } else {
        for (int i = base; i < e; i++) {
            int p = atomicAdd(&cursor[dst[i]], 1);
            col[p] = src[i];
        }
    }
}

// ---------------------------------------------------------------------------
// GEMM: hs[row,:] = (in[row,:] @ W) * (PRESCALE ? dis[row] : 1)
// Thread-per-row, W broadcast from shared, packed f32x2 FMAs.
// ---------------------------------------------------------------------------
template <int IN, int OUT, bool PRESCALE>
__global__ void gemm_kernel(const float* __restrict__ in,
                            const float* __restrict__ W,
                            const float* __restrict__ dis,
                            float* __restrict__ hs, int n) {
    __shared__ __align__(16) float sW[IN * OUT];
    for (int i = threadIdx.x; i < IN * OUT / 4; i += blockDim.x)
        reinterpret_cast<float4*>(sW)[i] = reinterpret_cast<const float4*>(W)[i];
    __syncthreads();

    int row = blockIdx.x * blockDim.x + threadIdx.x;
    if (row >= n) return;

    unsigned long long acc[OUT / 2];
#pragma unroll
    for (int c = 0; c < OUT / 2; c++) acc[c] = 0ULL;

    const float* xr = in + (size_t)row * IN;
    for (int k0 = 0; k0 < IN; k0 += 4) {
        float4 xv = *reinterpret_cast<const float4*>(xr + k0);
        float xs[4] = {xv.x, xv.y, xv.z, xv.w};
#pragma unroll
        for (int kk = 0; kk < 4; kk++) {
            unsigned long long xx = pack2(xs[kk], xs[kk]);
            const ulonglong2* wr =
                reinterpret_cast<const ulonglong2*>(sW + (k0 + kk) * OUT);
#pragma unroll
            for (int c4 = 0; c4 < OUT / 4; c4++) {
                ulonglong2 w = wr[c4];
                acc[c4 * 2 + 0] = ffma2(xx, w.x, acc[c4 * 2 + 0]);
                acc[c4 * 2 + 1] = ffma2(xx, w.y, acc[c4 * 2 + 1]);
            }
        }
    }

    ulonglong2* hp = reinterpret_cast<ulonglong2*>(hs + (size_t)row * OUT);
    if (PRESCALE) {
        float d = dis[row];
        unsigned long long dd = pack2(d, d);
#pragma unroll
        for (int c4 = 0; c4 < OUT / 4; c4++) {
            ulonglong2 r;
            r.x = fmul2(acc[c4 * 2 + 0], dd);
            r.y = fmul2(acc[c4 * 2 + 1], dd);
            hp[c4] = r;
        }
    } else {
#pragma unroll
        for (int c4 = 0; c4 < OUT / 4; c4++) {
            ulonglong2 r;
            r.x = acc[c4 * 2 + 0];
            r.y = acc[c4 * 2 + 1];
            hp[c4] = r;
        }
    }
}

// ---------------------------------------------------------------------------
// Gather + finalize. DIS_SRC: hs is unscaled, multiply each gathered value by
// dis[src] (layer 1, lets gemm1 run before dis exists). Otherwise hs is
// pre-scaled. out[d,:] = [relu]( dis[d]*acc + b ).
// ---------------------------------------------------------------------------
template <int OUT, bool RELU, bool DIS_SRC>
__global__ void gather_kernel(const int* __restrict__ rowptr,
                              const int* __restrict__ col,
                              const float* __restrict__ hs,
                              const float* __restrict__ dis,
                              const float* __restrict__ bias,
                              float* __restrict__ out, int n) {
    const int G = OUT / 4;
    int t = blockIdx.x * blockDim.x + threadIdx.x;
    int gid = t / G;
    int lane = t % G;
    if (gid >= n) return;

    const float4* hs4 = reinterpret_cast<const float4*>(hs);
    int beg = rowptr[gid];
    int end = rowptr[gid + 1];

    float dself = dis[gid];
    float4 a0 = hs4[(size_t)gid * G + lane];  // self term
    if (DIS_SRC) {
        a0.x *= dself; a0.y *= dself; a0.z *= dself; a0.w *= dself;
    }

#pragma unroll 4
    for (int e = beg; e < end; e++) {
        int s = __ldg(&col[e]);
        float4 v = hs4[(size_t)s * G + lane];
        if (DIS_SRC) {
            float ds = __ldg(&dis[s]);
            a0.x += v.x * ds; a0.y += v.y * ds;
            a0.z += v.z * ds; a0.w += v.w * ds;
        } else {
            a0.x += v.x; a0.y += v.y; a0.z += v.z; a0.w += v.w;
        }
    }

    float4 b4 = reinterpret_cast<const float4*>(bias)[lane];
    float4 r;
    r.x = a0.x * dself + b4.x;
    r.y = a0.y * dself + b4.y;
    r.z = a0.z * dself + b4.z;
    r.w = a0.w * dself + b4.w;
    if (RELU) {
        r.x = fmaxf(r.x, 0.0f);
        r.y = fmaxf(r.y, 0.0f);
        r.z = fmaxf(r.z, 0.0f);
        r.w = fmaxf(r.w, 0.0f);
    }
    reinterpret_cast<float4*>(out)[(size_t)gid * G + lane] = r;
}

// ---------------------------------------------------------------------------
// launch: CSR build on forked stream, gemm1 concurrent on main stream.
// ---------------------------------------------------------------------------
extern "C" void kernel_launch(void* const* d_in, const int* in_sizes, int n_in,
                              void* d_out, int out_size) {
    const float* x    = (const float*)d_in[0];
    const int*   eidx = (const int*)  d_in[1];
    const float* W1   = (const float*)d_in[2];
    const float* b1   = (const float*)d_in[3];
    const float* W2   = (const float*)d_in[4];
    const float* b2   = (const float*)d_in[5];
    const float* W3   = (const float*)d_in[6];
    const float* b3   = (const float*)d_in[7];

    const int N = in_sizes[0] / 128;
    const int E = in_sizes[1] / 2;
    const int* esrc = eidx;
    const int* edst = eidx + E;

    float *hs, *hA, *hB, *dis;
    int *deg, *scn, *bsum, *rowptr, *cursor, *col;
    cudaGetSymbolAddress((void**)&hs,     g_hs);
    cudaGetSymbolAddress((void**)&hA,     g_hA);
    cudaGetSymbolAddress((void**)&hB,     g_hB);
    cudaGetSymbolAddress((void**)&dis,    g_dis);
    cudaGetSymbolAddress((void**)&deg,    g_deg);
    cudaGetSymbolAddress((void**)&scn,    g_scan);
    cudaGetSymbolAddress((void**)&bsum,   g_bsum);
    cudaGetSymbolAddress((void**)&rowptr, g_rowptr);
    cudaGetSymbolAddress((void**)&cursor, g_cursor);
    cudaGetSymbolAddress((void**)&col,    g_col);

    float* out = (float*)d_out;
    const int T = 256;
    const int NB = (N + 1023) / 1024;
    const int EQ = (E + 3) / 4;

    // Fork a side stream for the CSR build (graph-capture-safe event fork).
    cudaStream_t s2;
    cudaEvent_t evFork, evJoin;
    cudaStreamCreateWithFlags(&s2, cudaStreamNonBlocking);
    cudaEventCreateWithFlags(&evFork, cudaEventDisableTiming);
    cudaEventCreateWithFlags(&evJoin, cudaEventDisableTiming);

    cudaEventRecord(evFork, 0);
    cudaStreamWaitEvent(s2, evFork, 0);

    // --- CSR build + normalization on s2 ---
    cudaMemsetAsync(deg, 0, (size_t)N * sizeof(int), s2);
    deg_count_kernel<<<(EQ + T - 1) / T, T, 0, s2>>>(edst, deg, E);
    scan1_kernel    <<<NB, 1024, 0, s2>>>(deg, scn, bsum, N);
    fixup_kernel    <<<(N + T - 1) / T, T, 0, s2>>>(scn, deg, bsum,
                                                    rowptr, cursor, dis, N, E);
    fill_kernel     <<<(EQ + T - 1) / T, T, 0, s2>>>(esrc, edst, cursor, col, E);
    cudaEventRecord(evJoin, s2);

    // --- gemm1 on main stream, concurrent with CSR build (no dis needed) ---
    gemm_kernel<128, 64, false><<<(N + 127) / 128, 128>>>(x, W1, nullptr, hs, N);

    // join
    cudaStreamWaitEvent(0, evJoin, 0);

    // --- layer 1 gather (dis applied on src side), relu ---
    gather_kernel<64, true, true><<<(N * 16 + T - 1) / T, T>>>(
        rowptr, col, hs, dis, b1, hA, N);

    // --- layer 2: 64 -> 64, relu (pre-scaled) ---
    gemm_kernel<64, 64, true><<<(N + 127) / 128, 128>>>(hA, W2, dis, hs, N);
    gather_kernel<64, true, false><<<(N * 16 + T - 1) / T, T>>>(
        rowptr, col, hs, dis, b2, hB, N);

    // --- layer 3: 64 -> 32, no relu ---
    gemm_kernel<64, 32, true><<<(N + 127) / 128, 128>>>(hB, W3, dis, hs, N);
    gather_kernel<32, false, false><<<(N * 8 + T - 1) / T, T>>>(
        rowptr, col, hs, dis, b3, out, N);

    // host-side cleanup of fork primitives (events already consumed in DAG)
    cudaEventDestroy(evFork);
    cudaEventDestroy(evJoin);
    cudaStreamDestroy(s2);
}